// round 1
// baseline (speedup 1.0000x reference)
#include <cuda_runtime.h>
#include <math.h>

#define BSZ 2
#define SEQ 2048
#define EMB 2048
#define NH 16
#define NKV 4
#define HD 128

// ---- scratch (static device memory; allocation APIs are forbidden) ----
__device__ float g_q[BSZ * SEQ * NH * HD];    // 33.5 MB
__device__ float g_k[BSZ * SEQ * NKV * HD];   //  8.4 MB
__device__ float g_v[BSZ * SEQ * NKV * HD];   //  8.4 MB
__device__ float g_att[BSZ * SEQ * NH * HD];  // 33.5 MB

// ============================================================================
// SGEMM: C[M,N] = A[M,K] @ B[K,N], row-major. M%128==0, N%128==0, K%16==0.
// 128x128 block tile, BK=16, 256 threads, 8x8 per-thread microtile.
// ============================================================================
__global__ __launch_bounds__(256) void sgemm_k(const float* __restrict__ A,
                                               const float* __restrict__ Bm,
                                               float* __restrict__ C,
                                               int M, int N, int K)
{
    __shared__ float As[16][132];   // transposed A tile, padded vs bank conflicts
    __shared__ float Bs[16][128];

    const int tid = threadIdx.x;
    const int ty = tid >> 4;        // 0..15 -> row group
    const int tx = tid & 15;        // 0..15 -> col group
    const int rowBase = blockIdx.y * 128;
    const int colBase = blockIdx.x * 128;

    float acc[8][8];
#pragma unroll
    for (int i = 0; i < 8; i++)
#pragma unroll
        for (int j = 0; j < 8; j++) acc[i][j] = 0.f;

    for (int kk = 0; kk < K; kk += 16) {
        // A tile: 128 rows x 16 cols  (512 float4, 2 per thread), store transposed
#pragma unroll
        for (int it = 0; it < 2; it++) {
            int lin = tid + it * 256;
            int r = lin >> 2, c4 = lin & 3;
            float4 v = *(const float4*)&A[(size_t)(rowBase + r) * K + kk + c4 * 4];
            As[c4 * 4 + 0][r] = v.x;
            As[c4 * 4 + 1][r] = v.y;
            As[c4 * 4 + 2][r] = v.z;
            As[c4 * 4 + 3][r] = v.w;
        }
        // B tile: 16 rows x 128 cols (512 float4, 2 per thread)
#pragma unroll
        for (int it = 0; it < 2; it++) {
            int lin = tid + it * 256;
            int r = lin >> 5, c4 = lin & 31;
            *(float4*)&Bs[r][c4 * 4] =
                *(const float4*)&Bm[(size_t)(kk + r) * N + colBase + c4 * 4];
        }
        __syncthreads();

#pragma unroll
        for (int k = 0; k < 16; k++) {
            float a[8], b[8];
            *(float4*)&a[0] = *(float4*)&As[k][ty * 8];
            *(float4*)&a[4] = *(float4*)&As[k][ty * 8 + 4];
            *(float4*)&b[0] = *(float4*)&Bs[k][tx * 8];
            *(float4*)&b[4] = *(float4*)&Bs[k][tx * 8 + 4];
#pragma unroll
            for (int i = 0; i < 8; i++)
#pragma unroll
                for (int j = 0; j < 8; j++)
                    acc[i][j] = fmaf(a[i], b[j], acc[i][j]);
        }
        __syncthreads();
    }

#pragma unroll
    for (int i = 0; i < 8; i++) {
        float* cp = &C[(size_t)(rowBase + ty * 8 + i) * N + colBase + tx * 8];
        float4 v0 = {acc[i][0], acc[i][1], acc[i][2], acc[i][3]};
        float4 v1 = {acc[i][4], acc[i][5], acc[i][6], acc[i][7]};
        *(float4*)cp = v0;
        *(float4*)(cp + 4) = v1;
    }
}

// ============================================================================
// RoPE (interleaved pair convention), in-place.
// Layout [b, s, h, 128]; pair p occupies elements 2p, 2p+1, so pair-linear
// index * 2 is the element offset directly.
// ============================================================================
__global__ void rope_k(float* __restrict__ t, const float* __restrict__ cs,
                       const float* __restrict__ sn, int nheads, int total)
{
    int idx = blockIdx.x * blockDim.x + threadIdx.x;
    if (idx >= total) return;
    int p = idx & 63;
    int s = ((idx >> 6) / nheads) % SEQ;
    float c = cs[s * 64 + p];
    float si = sn[s * 64 + p];
    int base = idx * 2;
    float tr = t[base], ti = t[base + 1];
    t[base]     = tr * c - ti * si;
    t[base + 1] = tr * si + ti * c;
}

// ============================================================================
// Flash attention (fp32, online softmax). BQ=64, BK=32, D=128.
// 256 threads. Q and K stored transposed in smem ([d][row]) for conflict-free
// vector reads in the score loop; V row-major for the PV loop.
// Per thread: S microtile = 4 rows x 2 keys; O microtile = 4 rows x 8 cols.
// ============================================================================
#define QT_S 68   // 64 + 4 pad
#define KT_S 36   // 32 + 4 pad
#define SS_S 36

__global__ __launch_bounds__(256) void flash_k(const float* __restrict__ Q,
                                               const float* __restrict__ K,
                                               const float* __restrict__ V,
                                               float* __restrict__ O)
{
    extern __shared__ float sm[];
    float* Qt  = sm;                   // 128 * 68
    float* Kt  = Qt + 128 * QT_S;      // 128 * 36
    float* Vs  = Kt + 128 * KT_S;      // 32 * 128
    float* Ssm = Vs + 32 * 128;        // 64 * 36
    float* m_s = Ssm + 64 * SS_S;      // 64
    float* l_s = m_s + 64;             // 64
    float* f_s = l_s + 64;             // 64

    const int tid  = threadIdx.x;
    const int qt   = blockIdx.x;       // query tile
    const int h    = blockIdx.y;
    const int b    = blockIdx.z;
    const int q0   = qt * 64;
    const int kh   = h >> 2;           // GQA: 4 q-heads share one kv-head
    const int rowg = tid >> 4;         // 0..15
    const int colg = tid & 15;         // 0..15
    const float scale = 0.08838834764831845f; // 1/sqrt(128)

    // load Q tile transposed: Qt[d][r]
    for (int i = tid; i < 64 * 32; i += 256) {
        int r = i >> 5, c4 = i & 31;
        float4 v = *(const float4*)&Q[(((size_t)b * SEQ + q0 + r) * NH + h) * HD + c4 * 4];
        Qt[(c4 * 4 + 0) * QT_S + r] = v.x;
        Qt[(c4 * 4 + 1) * QT_S + r] = v.y;
        Qt[(c4 * 4 + 2) * QT_S + r] = v.z;
        Qt[(c4 * 4 + 3) * QT_S + r] = v.w;
    }
    if (tid < 64) { m_s[tid] = -INFINITY; l_s[tid] = 0.f; }

    float o[4][8];
#pragma unroll
    for (int j = 0; j < 4; j++)
#pragma unroll
        for (int c = 0; c < 8; c++) o[j][c] = 0.f;

    __syncthreads();

    const int ntiles = 2 * qt + 2;     // keys 0 .. q0+63
    for (int t = 0; t < ntiles; t++) {
        const int k0 = t * 32;

        // load K (transposed) and V (row-major) tiles: 32 rows x 128
        for (int i = tid; i < 32 * 32; i += 256) {
            int r = i >> 5, c4 = i & 31;
            size_t gb = (((size_t)b * SEQ + k0 + r) * NKV + kh) * HD + c4 * 4;
            float4 kv = *(const float4*)&K[gb];
            Kt[(c4 * 4 + 0) * KT_S + r] = kv.x;
            Kt[(c4 * 4 + 1) * KT_S + r] = kv.y;
            Kt[(c4 * 4 + 2) * KT_S + r] = kv.z;
            Kt[(c4 * 4 + 3) * KT_S + r] = kv.w;
            *(float4*)&Vs[r * 128 + c4 * 4] = *(const float4*)&V[gb];
        }
        __syncthreads();

        // S = Q K^T : 4 rows x 2 keys per thread
        float sacc[4][2];
#pragma unroll
        for (int j = 0; j < 4; j++) { sacc[j][0] = 0.f; sacc[j][1] = 0.f; }

        const float* qp = &Qt[rowg * 4];
        const float* kp = &Kt[colg * 2];
#pragma unroll 4
        for (int d = 0; d < 128; d++) {
            float4 qa = *(const float4*)(qp + d * QT_S);
            float2 kb = *(const float2*)(kp + d * KT_S);
            sacc[0][0] = fmaf(qa.x, kb.x, sacc[0][0]);
            sacc[0][1] = fmaf(qa.x, kb.y, sacc[0][1]);
            sacc[1][0] = fmaf(qa.y, kb.x, sacc[1][0]);
            sacc[1][1] = fmaf(qa.y, kb.y, sacc[1][1]);
            sacc[2][0] = fmaf(qa.z, kb.x, sacc[2][0]);
            sacc[2][1] = fmaf(qa.z, kb.y, sacc[2][1]);
            sacc[3][0] = fmaf(qa.w, kb.x, sacc[3][0]);
            sacc[3][1] = fmaf(qa.w, kb.y, sacc[3][1]);
        }

        const bool maskt = (t >= 2 * qt);   // only last two tiles touch diagonal
#pragma unroll
        for (int j = 0; j < 4; j++) {
            int qi = q0 + rowg * 4 + j;
#pragma unroll
            for (int jj = 0; jj < 2; jj++) {
                int ki = k0 + colg * 2 + jj;
                float vv = sacc[j][jj] * scale;
                if (maskt && ki > qi) vv = -INFINITY;
                Ssm[(rowg * 4 + j) * SS_S + colg * 2 + jj] = vv;
            }
        }
        __syncthreads();

        // online softmax row pass (one thread per query row)
        if (tid < 64) {
            float mold = m_s[tid];
            float mx = mold;
            float* srow = &Ssm[tid * SS_S];
#pragma unroll
            for (int k2 = 0; k2 < 32; k2++) mx = fmaxf(mx, srow[k2]);
            float f = __expf(mold - mx);    // mold=-inf on first tile -> f=0
            float sum = 0.f;
#pragma unroll
            for (int k2 = 0; k2 < 32; k2++) {
                float p = __expf(srow[k2] - mx);
                srow[k2] = p;
                sum += p;
            }
            l_s[tid] = l_s[tid] * f + sum;
            m_s[tid] = mx;
            f_s[tid] = f;
        }
        __syncthreads();

        // rescale O, accumulate P @ V
#pragma unroll
        for (int j = 0; j < 4; j++) {
            float f = f_s[rowg * 4 + j];
#pragma unroll
            for (int c = 0; c < 8; c++) o[j][c] *= f;
        }
#pragma unroll 2
        for (int k2 = 0; k2 < 32; k2++) {
            float4 v0 = *(const float4*)&Vs[k2 * 128 + colg * 8];
            float4 v1 = *(const float4*)&Vs[k2 * 128 + colg * 8 + 4];
#pragma unroll
            for (int j = 0; j < 4; j++) {
                float p = Ssm[(rowg * 4 + j) * SS_S + k2];
                o[j][0] = fmaf(p, v0.x, o[j][0]);
                o[j][1] = fmaf(p, v0.y, o[j][1]);
                o[j][2] = fmaf(p, v0.z, o[j][2]);
                o[j][3] = fmaf(p, v0.w, o[j][3]);
                o[j][4] = fmaf(p, v1.x, o[j][4]);
                o[j][5] = fmaf(p, v1.y, o[j][5]);
                o[j][6] = fmaf(p, v1.z, o[j][6]);
                o[j][7] = fmaf(p, v1.w, o[j][7]);
            }
        }
        __syncthreads();
    }

    // normalize and store
#pragma unroll
    for (int j = 0; j < 4; j++) {
        float inv = 1.f / l_s[rowg * 4 + j];
        float* op = &O[(((size_t)b * SEQ + q0 + rowg * 4 + j) * NH + h) * HD + colg * 8];
        float4 w0 = {o[j][0] * inv, o[j][1] * inv, o[j][2] * inv, o[j][3] * inv};
        float4 w1 = {o[j][4] * inv, o[j][5] * inv, o[j][6] * inv, o[j][7] * inv};
        *(float4*)op = w0;
        *(float4*)(op + 4) = w1;
    }
}

// ============================================================================
// launch
// ============================================================================
extern "C" void kernel_launch(void* const* d_in, const int* in_sizes, int n_in,
                              void* d_out, int out_size)
{
    const float* x  = (const float*)d_in[0];
    const float* cs = (const float*)d_in[1];
    const float* sn = (const float*)d_in[2];
    const float* wq = (const float*)d_in[3];
    const float* wk = (const float*)d_in[4];
    const float* wv = (const float*)d_in[5];
    const float* wo = (const float*)d_in[6];
    float* out = (float*)d_out;

    float *q, *k, *v, *att;
    cudaGetSymbolAddress((void**)&q,   g_q);
    cudaGetSymbolAddress((void**)&k,   g_k);
    cudaGetSymbolAddress((void**)&v,   g_v);
    cudaGetSymbolAddress((void**)&att, g_att);

    const int smem = (128 * QT_S + 128 * KT_S + 32 * 128 + 64 * SS_S + 192) * (int)sizeof(float);
    cudaFuncSetAttribute(flash_k, cudaFuncAttributeMaxDynamicSharedMemorySize, smem);

    const int M = BSZ * SEQ;  // 4096

    sgemm_k<<<dim3(EMB / 128, M / 128), 256>>>(x, wq, q, M, EMB, EMB);
    sgemm_k<<<dim3((NKV * HD) / 128, M / 128), 256>>>(x, wk, k, M, NKV * HD, EMB);
    sgemm_k<<<dim3((NKV * HD) / 128, M / 128), 256>>>(x, wv, v, M, NKV * HD, EMB);

    rope_k<<<(M * NH  * 64 + 255) / 256, 256>>>(q, cs, sn, NH,  M * NH  * 64);
    rope_k<<<(M * NKV * 64 + 255) / 256, 256>>>(k, cs, sn, NKV, M * NKV * 64);

    flash_k<<<dim3(SEQ / 64, NH, BSZ), 256, smem>>>(q, k, v, att);

    sgemm_k<<<dim3(EMB / 128, M / 128), 256>>>(att, wo, out, M, EMB, EMB);
}

// round 6
// speedup vs baseline: 2.6322x; 2.6322x over previous
#include <cuda_runtime.h>
#include <cuda_bf16.h>
#include <cstdint>
#include <math.h>

#define BSZ 2
#define SEQ 2048
#define EMB 2048
#define NH 16
#define NKV 4
#define HD 128

typedef __nv_bfloat16 bf16;

// ---- scratch (static device memory; allocation APIs are forbidden) ----
__device__ float g_q[BSZ * SEQ * NH * HD];
__device__ float g_k[BSZ * SEQ * NKV * HD];
__device__ float g_v[BSZ * SEQ * NKV * HD];

__device__ bf16 g_xh[BSZ * SEQ * EMB];
__device__ bf16 g_xl[BSZ * SEQ * EMB];
__device__ bf16 g_qh[BSZ * SEQ * NH * HD];
__device__ bf16 g_ql[BSZ * SEQ * NH * HD];
__device__ bf16 g_kh[BSZ * SEQ * NKV * HD];
__device__ bf16 g_kl[BSZ * SEQ * NKV * HD];
__device__ bf16 g_vh[BSZ * SEQ * NKV * HD];
__device__ bf16 g_vl[BSZ * SEQ * NKV * HD];
__device__ bf16 g_ath[BSZ * SEQ * EMB];
__device__ bf16 g_atl[BSZ * SEQ * EMB];
__device__ bf16 g_wqth[EMB * EMB];
__device__ bf16 g_wqtl[EMB * EMB];
__device__ bf16 g_wkth[NKV * HD * EMB];
__device__ bf16 g_wktl[NKV * HD * EMB];
__device__ bf16 g_wvth[NKV * HD * EMB];
__device__ bf16 g_wvtl[NKV * HD * EMB];
__device__ bf16 g_woth[EMB * EMB];
__device__ bf16 g_wotl[EMB * EMB];

// ============================================================================
// warp-mma helpers (sm_80+ path; tcgen05 unavailable at .target sm_103)
// ============================================================================
__device__ __forceinline__ uint32_t smem_u32(const void* p) {
    uint32_t a;
    asm("{ .reg .u64 t; cvta.to.shared.u64 t, %1; cvt.u32.u64 %0, t; }" : "=r"(a) : "l"(p));
    return a;
}
__device__ __forceinline__ void mma_bf16(float* c, const uint32_t* a, const uint32_t* b) {
    asm volatile(
        "mma.sync.aligned.m16n8k16.row.col.f32.bf16.bf16.f32 "
        "{%0,%1,%2,%3}, {%4,%5,%6,%7}, {%8,%9}, {%0,%1,%2,%3};"
        : "+f"(c[0]), "+f"(c[1]), "+f"(c[2]), "+f"(c[3])
        : "r"(a[0]), "r"(a[1]), "r"(a[2]), "r"(a[3]), "r"(b[0]), "r"(b[1]));
}
__device__ __forceinline__ void ldsm4(uint32_t* r, uint32_t addr) {
    asm volatile("ldmatrix.sync.aligned.m8n8.x4.shared.b16 {%0,%1,%2,%3}, [%4];"
                 : "=r"(r[0]), "=r"(r[1]), "=r"(r[2]), "=r"(r[3]) : "r"(addr));
}
__device__ __forceinline__ void ldsm2(uint32_t* r, uint32_t addr) {
    asm volatile("ldmatrix.sync.aligned.m8n8.x2.shared.b16 {%0,%1}, [%2];"
                 : "=r"(r[0]), "=r"(r[1]) : "r"(addr));
}
__device__ __forceinline__ void ldsm2t(uint32_t* r, uint32_t addr) {
    asm volatile("ldmatrix.sync.aligned.m8n8.x2.trans.shared.b16 {%0,%1}, [%2];"
                 : "=r"(r[0]), "=r"(r[1]) : "r"(addr));
}
__device__ __forceinline__ uint32_t pack2bf(bf16 lo, bf16 hi) {
    __nv_bfloat162 t(lo, hi);
    return *reinterpret_cast<uint32_t*>(&t);
}

// ============================================================================
// Split fp32 -> bf16 hi + bf16 lo (elementwise)
// ============================================================================
__global__ void asplit_k(const float* __restrict__ A, bf16* __restrict__ H,
                         bf16* __restrict__ L, int n)
{
    int i = blockIdx.x * blockDim.x + threadIdx.x;
    if (i >= n) return;
    float v = A[i];
    bf16 h = __float2bfloat16_rn(v);
    H[i] = h;
    L[i] = __float2bfloat16_rn(v - __bfloat162float(h));
}

// ============================================================================
// Transpose + split: W[K,N] fp32 -> Th[N,K], Tl[N,K] bf16
// ============================================================================
__global__ void wsplit_t_k(const float* __restrict__ W, bf16* __restrict__ Th,
                           bf16* __restrict__ Tl, int K, int N)
{
    __shared__ float t[32][33];
    int n0 = blockIdx.x * 32, k0 = blockIdx.y * 32;
    int tx = threadIdx.x, ty = threadIdx.y;  // 32 x 8
#pragma unroll
    for (int j = 0; j < 32; j += 8)
        t[ty + j][tx] = W[(size_t)(k0 + ty + j) * N + n0 + tx];
    __syncthreads();
#pragma unroll
    for (int j = 0; j < 32; j += 8) {
        float v = t[tx][ty + j];
        bf16 h = __float2bfloat16_rn(v);
        size_t o = (size_t)(n0 + ty + j) * K + k0 + tx;
        Th[o] = h;
        Tl[o] = __float2bfloat16_rn(v - __bfloat162float(h));
    }
}

// ============================================================================
// RoPE + split: fp32 t (post-GEMM) -> bf16 hi/lo, rotated. total = #pairs.
// ============================================================================
__global__ void rope_split_k(const float* __restrict__ t, const float* __restrict__ cs,
                             const float* __restrict__ sn, bf16* __restrict__ H,
                             bf16* __restrict__ L, int nheads, int total)
{
    int idx = blockIdx.x * blockDim.x + threadIdx.x;
    if (idx >= total) return;
    int p = idx & 63;
    int s = ((idx >> 6) / nheads) % SEQ;
    float c = cs[s * 64 + p];
    float si = sn[s * 64 + p];
    int base = idx * 2;
    float tr = t[base], ti = t[base + 1];
    float a = tr * c - ti * si;
    float b2 = tr * si + ti * c;
    bf16 ah = __float2bfloat16_rn(a);
    bf16 bh = __float2bfloat16_rn(b2);
    H[base] = ah;     L[base] = __float2bfloat16_rn(a - __bfloat162float(ah));
    H[base + 1] = bh; L[base + 1] = __float2bfloat16_rn(b2 - __bfloat162float(bh));
}

// ============================================================================
// bf16-split GEMM on mma.sync: C[M,N](f32) = (Ah+Al)[M,K] x (Bh+Bl)[N,K]^T
// 128x128 tile, BK=32, 256 threads, warp grid 2(M)x4(N), warp tile 64x32.
// ============================================================================
#define GSTR 40  // smem row stride in elems (32 + 8 pad -> conflict-free ldmatrix)

__global__ __launch_bounds__(256) void gemm_mma(const bf16* __restrict__ Ah,
                                                const bf16* __restrict__ Al,
                                                const bf16* __restrict__ Bh,
                                                const bf16* __restrict__ Bl,
                                                float* __restrict__ C,
                                                int M, int N, int K)
{
    __shared__ bf16 sAh[128 * GSTR], sAl[128 * GSTR], sBh[128 * GSTR], sBl[128 * GSTR];

    const int tid = threadIdx.x, lane = tid & 31, warp = tid >> 5;
    const int wm = warp >> 2;       // 0..1 -> M offset wm*64
    const int wn = warp & 3;        // 0..3 -> N offset wn*32
    const int mB = blockIdx.y * 128, nB = blockIdx.x * 128;

    float c[4][4][4];
#pragma unroll
    for (int i = 0; i < 4; i++)
#pragma unroll
        for (int j = 0; j < 4; j++)
#pragma unroll
            for (int e = 0; e < 4; e++) c[i][j][e] = 0.f;

    // each thread owns 2 16B chunks per tensor per iteration
    uint4 rAh[2], rAl[2], rBh[2], rBl[2];
    int crow[2], ckc[2];
#pragma unroll
    for (int j = 0; j < 2; j++) {
        int chunk = tid + j * 256;
        crow[j] = chunk >> 2;          // 0..127
        ckc[j]  = (chunk & 3) * 8;     // elem offset in row (0,8,16,24)
    }

    auto loadg = [&](int kk) {
#pragma unroll
        for (int j = 0; j < 2; j++) {
            size_t ga = (size_t)(mB + crow[j]) * K + kk + ckc[j];
            size_t gb = (size_t)(nB + crow[j]) * K + kk + ckc[j];
            rAh[j] = *(const uint4*)&Ah[ga];
            rAl[j] = *(const uint4*)&Al[ga];
            rBh[j] = *(const uint4*)&Bh[gb];
            rBl[j] = *(const uint4*)&Bl[gb];
        }
    };

    loadg(0);
    for (int kk = 0; kk < K; kk += 32) {
        __syncthreads();
#pragma unroll
        for (int j = 0; j < 2; j++) {
            int s = crow[j] * GSTR + ckc[j];
            *(uint4*)&sAh[s] = rAh[j];
            *(uint4*)&sAl[s] = rAl[j];
            *(uint4*)&sBh[s] = rBh[j];
            *(uint4*)&sBl[s] = rBl[j];
        }
        __syncthreads();
        if (kk + 32 < K) loadg(kk + 32);

#pragma unroll
        for (int ks = 0; ks < 2; ks++) {
            uint32_t fAh[4][4], fAl[4][4], fBh[4][2], fBl[4][2];
#pragma unroll
            for (int mt = 0; mt < 4; mt++) {
                int e = (wm * 64 + mt * 16 + (lane & 15)) * GSTR + ks * 16 + (lane >> 4) * 8;
                ldsm4(fAh[mt], smem_u32(&sAh[e]));
                ldsm4(fAl[mt], smem_u32(&sAl[e]));
            }
#pragma unroll
            for (int nt = 0; nt < 4; nt++) {
                int e = (wn * 32 + nt * 8 + (lane & 7)) * GSTR + ks * 16 + ((lane >> 3) & 1) * 8;
                ldsm2(fBh[nt], smem_u32(&sBh[e]));
                ldsm2(fBl[nt], smem_u32(&sBl[e]));
            }
#pragma unroll
            for (int mt = 0; mt < 4; mt++)
#pragma unroll
                for (int nt = 0; nt < 4; nt++) {
                    mma_bf16(c[mt][nt], fAh[mt], fBh[nt]);
                    mma_bf16(c[mt][nt], fAh[mt], fBl[nt]);
                    mma_bf16(c[mt][nt], fAl[mt], fBh[nt]);
                }
        }
    }

    // epilogue
#pragma unroll
    for (int mt = 0; mt < 4; mt++)
#pragma unroll
        for (int nt = 0; nt < 4; nt++) {
            int row = mB + wm * 64 + mt * 16 + (lane >> 2);
            int col = nB + wn * 32 + nt * 8 + (lane & 3) * 2;
            float2 v0 = {c[mt][nt][0], c[mt][nt][1]};
            float2 v1 = {c[mt][nt][2], c[mt][nt][3]};
            *(float2*)&C[(size_t)row * N + col] = v0;
            *(float2*)&C[(size_t)(row + 8) * N + col] = v1;
        }
}

// ============================================================================
// Flash attention on mma.sync, bf16-split. BQ=128 (warp = 16 rows), BKV=64.
// Q/K smem K-major (ldmatrix), V smem natural [key][d] (ldmatrix.trans).
// P reuses S C-fragments as A-fragments directly (no smem round trip).
// Writes bf16 hi/lo attention output for the final GEMM.
// ============================================================================
#define FSTR 136  // 128 + 8 pad
#define FQH 0
#define FQL (128 * FSTR)
#define FKH (2 * 128 * FSTR)
#define FKL (FKH + 64 * FSTR)
#define FVH (FKL + 64 * FSTR)
#define FVL (FVH + 64 * FSTR)
#define FSM_ELEMS (FVL + 64 * FSTR)   // 69632 elems = 139264 B

__global__ __launch_bounds__(256) void flash_mma(const bf16* __restrict__ Qh,
                                                 const bf16* __restrict__ Ql,
                                                 const bf16* __restrict__ Kh,
                                                 const bf16* __restrict__ Kl,
                                                 const bf16* __restrict__ Vh,
                                                 const bf16* __restrict__ Vl,
                                                 bf16* __restrict__ Oh,
                                                 bf16* __restrict__ Ol)
{
    extern __shared__ bf16 fsm[];
    const int tid = threadIdx.x, lane = tid & 31, warp = tid >> 5;
    const int qt = blockIdx.x, h = blockIdx.y, b = blockIdx.z;
    const int q0 = qt * 128;
    const int khead = h >> 2;
    const float scale = 0.08838834764831845f;

    // load Q tile (128 x 128, hi+lo)
    for (int cidx = tid; cidx < 2048; cidx += 256) {
        int row = cidx >> 4, kc = (cidx & 15) * 8;
        size_t g = (size_t)(b * SEQ + q0 + row) * (NH * HD) + h * HD + kc;
        int s = row * FSTR + kc;
        *(uint4*)&fsm[FQH + s] = *(const uint4*)&Qh[g];
        *(uint4*)&fsm[FQL + s] = *(const uint4*)&Ql[g];
    }

    float o[16][4];
#pragma unroll
    for (int i = 0; i < 16; i++)
#pragma unroll
        for (int e = 0; e < 4; e++) o[i][e] = 0.f;
    float mrow[2] = {-1e30f, -1e30f}, lrow[2] = {0.f, 0.f};

    const int ntiles = 2 * qt + 2;
    for (int t = 0; t < ntiles; t++) {
        const int k0 = t * 64;
        __syncthreads();   // protect K/V smem from previous iteration's readers
        for (int cidx = tid; cidx < 1024; cidx += 256) {
            int row = cidx >> 4, kc = (cidx & 15) * 8;
            size_t g = (size_t)(b * SEQ + k0 + row) * (NKV * HD) + khead * HD + kc;
            int s = row * FSTR + kc;
            *(uint4*)&fsm[FKH + s] = *(const uint4*)&Kh[g];
            *(uint4*)&fsm[FKL + s] = *(const uint4*)&Kl[g];
            *(uint4*)&fsm[FVH + s] = *(const uint4*)&Vh[g];
            *(uint4*)&fsm[FVL + s] = *(const uint4*)&Vl[g];
        }
        __syncthreads();

        // ---- S = Q K^T (warp rows x 64 keys), 3-product split ----
        float s[8][4];
#pragma unroll
        for (int i = 0; i < 8; i++)
#pragma unroll
            for (int e = 0; e < 4; e++) s[i][e] = 0.f;

#pragma unroll
        for (int ks = 0; ks < 8; ks++) {
            uint32_t qfh[4], qfl[4];
            int qa = (warp * 16 + (lane & 15)) * FSTR + ks * 16 + (lane >> 4) * 8;
            ldsm4(qfh, smem_u32(&fsm[FQH + qa]));
            ldsm4(qfl, smem_u32(&fsm[FQL + qa]));
#pragma unroll
            for (int nt = 0; nt < 8; nt++) {
                uint32_t kfh[2], kfl[2];
                int ka = (nt * 8 + (lane & 7)) * FSTR + ks * 16 + ((lane >> 3) & 1) * 8;
                ldsm2(kfh, smem_u32(&fsm[FKH + ka]));
                ldsm2(kfl, smem_u32(&fsm[FKL + ka]));
                mma_bf16(s[nt], qfh, kfh);
                mma_bf16(s[nt], qfh, kfl);
                mma_bf16(s[nt], qfl, kfh);
            }
        }

        // ---- scale + causal mask ----
        const int r0 = q0 + warp * 16 + (lane >> 2);
        const bool needmask = (t >= ntiles - 2);
#pragma unroll
        for (int nt = 0; nt < 8; nt++) {
#pragma unroll
            for (int e = 0; e < 4; e++) {
                float v = s[nt][e] * scale;
                if (needmask) {
                    int col = k0 + nt * 8 + (lane & 3) * 2 + (e & 1);
                    int row = r0 + ((e >> 1) << 3);
                    if (col > row) v = -1e30f;
                }
                s[nt][e] = v;
            }
        }

        // ---- online softmax (rows r0 and r0+8, reduced over quad lanes) ----
        float mx0 = -1e30f, mx1 = -1e30f;
#pragma unroll
        for (int nt = 0; nt < 8; nt++) {
            mx0 = fmaxf(mx0, fmaxf(s[nt][0], s[nt][1]));
            mx1 = fmaxf(mx1, fmaxf(s[nt][2], s[nt][3]));
        }
        mx0 = fmaxf(mx0, __shfl_xor_sync(0xffffffff, mx0, 1));
        mx0 = fmaxf(mx0, __shfl_xor_sync(0xffffffff, mx0, 2));
        mx1 = fmaxf(mx1, __shfl_xor_sync(0xffffffff, mx1, 1));
        mx1 = fmaxf(mx1, __shfl_xor_sync(0xffffffff, mx1, 2));
        float mn0 = fmaxf(mrow[0], mx0), mn1 = fmaxf(mrow[1], mx1);
        float f0 = __expf(mrow[0] - mn0), f1 = __expf(mrow[1] - mn1);

        float sum0 = 0.f, sum1 = 0.f;
#pragma unroll
        for (int nt = 0; nt < 8; nt++) {
            s[nt][0] = __expf(s[nt][0] - mn0);
            s[nt][1] = __expf(s[nt][1] - mn0);
            s[nt][2] = __expf(s[nt][2] - mn1);
            s[nt][3] = __expf(s[nt][3] - mn1);
            sum0 += s[nt][0] + s[nt][1];
            sum1 += s[nt][2] + s[nt][3];
        }
        sum0 += __shfl_xor_sync(0xffffffff, sum0, 1);
        sum0 += __shfl_xor_sync(0xffffffff, sum0, 2);
        sum1 += __shfl_xor_sync(0xffffffff, sum1, 1);
        sum1 += __shfl_xor_sync(0xffffffff, sum1, 2);
        lrow[0] = lrow[0] * f0 + sum0;
        lrow[1] = lrow[1] * f1 + sum1;
        mrow[0] = mn0;
        mrow[1] = mn1;

        // ---- rescale O ----
#pragma unroll
        for (int nt = 0; nt < 16; nt++) {
            o[nt][0] *= f0; o[nt][1] *= f0;
            o[nt][2] *= f1; o[nt][3] *= f1;
        }

        // ---- O += P V : P from S fragments (hi + lo split) ----
#pragma unroll
        for (int ks = 0; ks < 4; ks++) {
            uint32_t ph[4], pl[4];
#pragma unroll
            for (int half = 0; half < 2; half++) {
                int ti2 = 2 * ks + half;
                bf16 h0 = __float2bfloat16_rn(s[ti2][0]);
                bf16 h1 = __float2bfloat16_rn(s[ti2][1]);
                bf16 h2 = __float2bfloat16_rn(s[ti2][2]);
                bf16 h3 = __float2bfloat16_rn(s[ti2][3]);
                ph[2 * half]     = pack2bf(h0, h1);
                ph[2 * half + 1] = pack2bf(h2, h3);
                pl[2 * half]     = pack2bf(__float2bfloat16_rn(s[ti2][0] - __bfloat162float(h0)),
                                           __float2bfloat16_rn(s[ti2][1] - __bfloat162float(h1)));
                pl[2 * half + 1] = pack2bf(__float2bfloat16_rn(s[ti2][2] - __bfloat162float(h2)),
                                           __float2bfloat16_rn(s[ti2][3] - __bfloat162float(h3)));
            }
#pragma unroll
            for (int nt = 0; nt < 16; nt++) {
                uint32_t vfh[2], vfl[2];
                int va = (ks * 16 + (lane & 15)) * FSTR + nt * 8;
                ldsm2t(vfh, smem_u32(&fsm[FVH + va]));
                ldsm2t(vfl, smem_u32(&fsm[FVL + va]));
                mma_bf16(o[nt], ph, vfh);
                mma_bf16(o[nt], ph, vfl);
                mma_bf16(o[nt], pl, vfh);
            }
        }
    }

    // ---- finalize: divide by l, write bf16 hi/lo ----
    float inv0 = 1.f / lrow[0], inv1 = 1.f / lrow[1];
    const size_t tok0 = (size_t)(b * SEQ + q0 + warp * 16 + (lane >> 2));
#pragma unroll
    for (int nt = 0; nt < 16; nt++) {
        int col = h * HD + nt * 8 + (lane & 3) * 2;
        float v0 = o[nt][0] * inv0, v1 = o[nt][1] * inv0;
        float v2 = o[nt][2] * inv1, v3 = o[nt][3] * inv1;
        bf16 h0 = __float2bfloat16_rn(v0), h1 = __float2bfloat16_rn(v1);
        bf16 h2 = __float2bfloat16_rn(v2), h3 = __float2bfloat16_rn(v3);
        size_t a0 = tok0 * EMB + col;
        size_t a1 = (tok0 + 8) * EMB + col;
        *(uint32_t*)&Oh[a0] = pack2bf(h0, h1);
        *(uint32_t*)&Oh[a1] = pack2bf(h2, h3);
        *(uint32_t*)&Ol[a0] = pack2bf(__float2bfloat16_rn(v0 - __bfloat162float(h0)),
                                      __float2bfloat16_rn(v1 - __bfloat162float(h1)));
        *(uint32_t*)&Ol[a1] = pack2bf(__float2bfloat16_rn(v2 - __bfloat162float(h2)),
                                      __float2bfloat16_rn(v3 - __bfloat162float(h3)));
    }
}

// ============================================================================
// launch
// ============================================================================
extern "C" void kernel_launch(void* const* d_in, const int* in_sizes, int n_in,
                              void* d_out, int out_size)
{
    const float* x  = (const float*)d_in[0];
    const float* cs = (const float*)d_in[1];
    const float* sn = (const float*)d_in[2];
    const float* wq = (const float*)d_in[3];
    const float* wk = (const float*)d_in[4];
    const float* wv = (const float*)d_in[5];
    const float* wo = (const float*)d_in[6];
    float* out = (float*)d_out;

    float *q, *k, *v;
    cudaGetSymbolAddress((void**)&q, g_q);
    cudaGetSymbolAddress((void**)&k, g_k);
    cudaGetSymbolAddress((void**)&v, g_v);

    bf16 *xh, *xl, *qh, *ql, *kh, *kl, *vh, *vl, *ath, *atl;
    bf16 *wqth, *wqtl, *wkth, *wktl, *wvth, *wvtl, *woth, *wotl;
    cudaGetSymbolAddress((void**)&xh,  g_xh);
    cudaGetSymbolAddress((void**)&xl,  g_xl);
    cudaGetSymbolAddress((void**)&qh,  g_qh);
    cudaGetSymbolAddress((void**)&ql,  g_ql);
    cudaGetSymbolAddress((void**)&kh,  g_kh);
    cudaGetSymbolAddress((void**)&kl,  g_kl);
    cudaGetSymbolAddress((void**)&vh,  g_vh);
    cudaGetSymbolAddress((void**)&vl,  g_vl);
    cudaGetSymbolAddress((void**)&ath, g_ath);
    cudaGetSymbolAddress((void**)&atl, g_atl);
    cudaGetSymbolAddress((void**)&wqth, g_wqth);
    cudaGetSymbolAddress((void**)&wqtl, g_wqtl);
    cudaGetSymbolAddress((void**)&wkth, g_wkth);
    cudaGetSymbolAddress((void**)&wktl, g_wktl);
    cudaGetSymbolAddress((void**)&wvth, g_wvth);
    cudaGetSymbolAddress((void**)&wvtl, g_wvtl);
    cudaGetSymbolAddress((void**)&woth, g_woth);
    cudaGetSymbolAddress((void**)&wotl, g_wotl);

    const int fsmem = FSM_ELEMS * (int)sizeof(bf16);   // 139264 B
    cudaFuncSetAttribute(flash_mma, cudaFuncAttributeMaxDynamicSharedMemorySize, fsmem);

    const int M = BSZ * SEQ;   // 4096
    const int NKVD = NKV * HD; // 512

    // splits
    asplit_k<<<(M * EMB + 255) / 256, 256>>>(x, xh, xl, M * EMB);
    wsplit_t_k<<<dim3(EMB / 32, EMB / 32),  dim3(32, 8)>>>(wq, wqth, wqtl, EMB, EMB);
    wsplit_t_k<<<dim3(NKVD / 32, EMB / 32), dim3(32, 8)>>>(wk, wkth, wktl, EMB, NKVD);
    wsplit_t_k<<<dim3(NKVD / 32, EMB / 32), dim3(32, 8)>>>(wv, wvth, wvtl, EMB, NKVD);
    wsplit_t_k<<<dim3(EMB / 32, EMB / 32),  dim3(32, 8)>>>(wo, woth, wotl, EMB, EMB);

    // QKV projections (tensor cores)
    gemm_mma<<<dim3(EMB / 128, M / 128), 256>>>(xh, xl, wqth, wqtl, q, M, EMB, EMB);
    gemm_mma<<<dim3(NKVD / 128, M / 128), 256>>>(xh, xl, wkth, wktl, k, M, NKVD, EMB);
    gemm_mma<<<dim3(NKVD / 128, M / 128), 256>>>(xh, xl, wvth, wvtl, v, M, NKVD, EMB);

    // rope + split to bf16
    rope_split_k<<<(M * NH * 64 + 255) / 256, 256>>>(q, cs, sn, qh, ql, NH, M * NH * 64);
    rope_split_k<<<(M * NKV * 64 + 255) / 256, 256>>>(k, cs, sn, kh, kl, NKV, M * NKV * 64);
    asplit_k<<<(M * NKVD + 255) / 256, 256>>>(v, vh, vl, M * NKVD);

    // attention (tensor cores), writes split bf16 output
    flash_mma<<<dim3(SEQ / 128, NH, BSZ), 256, fsmem>>>(qh, ql, kh, kl, vh, vl, ath, atl);

    // out projection (tensor cores)
    gemm_mma<<<dim3(EMB / 128, M / 128), 256>>>(ath, atl, woth, wotl, out, M, EMB, EMB);
}

// round 7
// speedup vs baseline: 2.7286x; 1.0366x over previous
#include <cuda_runtime.h>
#include <cuda_bf16.h>
#include <cstdint>
#include <math.h>

#define BSZ 2
#define SEQ 2048
#define EMB 2048
#define NH 16
#define NKV 4
#define HD 128

typedef __nv_bfloat16 bf16;

// ---- scratch (static device memory; allocation APIs are forbidden) ----
__device__ float g_q[BSZ * SEQ * NH * HD];
__device__ float g_k[BSZ * SEQ * NKV * HD];
__device__ float g_v[BSZ * SEQ * NKV * HD];

__device__ bf16 g_xh[BSZ * SEQ * EMB];
__device__ bf16 g_xl[BSZ * SEQ * EMB];
__device__ bf16 g_qh[BSZ * SEQ * NH * HD];
__device__ bf16 g_ql[BSZ * SEQ * NH * HD];
__device__ bf16 g_kh[BSZ * SEQ * NKV * HD];
__device__ bf16 g_kl[BSZ * SEQ * NKV * HD];
__device__ bf16 g_vh[BSZ * SEQ * NKV * HD];
__device__ bf16 g_vl[BSZ * SEQ * NKV * HD];
__device__ bf16 g_ath[BSZ * SEQ * EMB];
__device__ bf16 g_atl[BSZ * SEQ * EMB];
__device__ bf16 g_wqth[EMB * EMB];
__device__ bf16 g_wqtl[EMB * EMB];
__device__ bf16 g_wkth[NKV * HD * EMB];
__device__ bf16 g_wktl[NKV * HD * EMB];
__device__ bf16 g_wvth[NKV * HD * EMB];
__device__ bf16 g_wvtl[NKV * HD * EMB];
__device__ bf16 g_woth[EMB * EMB];
__device__ bf16 g_wotl[EMB * EMB];

// ============================================================================
// warp-mma helpers (sm_80+ path; tcgen05 unavailable at .target sm_103)
// ============================================================================
__device__ __forceinline__ uint32_t smem_u32(const void* p) {
    uint32_t a;
    asm("{ .reg .u64 t; cvta.to.shared.u64 t, %1; cvt.u32.u64 %0, t; }" : "=r"(a) : "l"(p));
    return a;
}
__device__ __forceinline__ void mma_bf16(float* c, const uint32_t* a, const uint32_t* b) {
    asm volatile(
        "mma.sync.aligned.m16n8k16.row.col.f32.bf16.bf16.f32 "
        "{%0,%1,%2,%3}, {%4,%5,%6,%7}, {%8,%9}, {%0,%1,%2,%3};"
        : "+f"(c[0]), "+f"(c[1]), "+f"(c[2]), "+f"(c[3])
        : "r"(a[0]), "r"(a[1]), "r"(a[2]), "r"(a[3]), "r"(b[0]), "r"(b[1]));
}
__device__ __forceinline__ void ldsm4(uint32_t* r, uint32_t addr) {
    asm volatile("ldmatrix.sync.aligned.m8n8.x4.shared.b16 {%0,%1,%2,%3}, [%4];"
                 : "=r"(r[0]), "=r"(r[1]), "=r"(r[2]), "=r"(r[3]) : "r"(addr));
}
__device__ __forceinline__ void ldsm4t(uint32_t* r, uint32_t addr) {
    asm volatile("ldmatrix.sync.aligned.m8n8.x4.trans.shared.b16 {%0,%1,%2,%3}, [%4];"
                 : "=r"(r[0]), "=r"(r[1]), "=r"(r[2]), "=r"(r[3]) : "r"(addr));
}
__device__ __forceinline__ uint32_t pack2bf(bf16 lo, bf16 hi) {
    __nv_bfloat162 t(lo, hi);
    return *reinterpret_cast<uint32_t*>(&t);
}
// cp.async 16B
__device__ __forceinline__ void cpa16(uint32_t s, const void* g) {
    asm volatile("cp.async.cg.shared.global [%0], [%1], 16;" :: "r"(s), "l"(g));
}
__device__ __forceinline__ void cpa_commit() { asm volatile("cp.async.commit_group;" ::: "memory"); }
__device__ __forceinline__ void cpa_wait0()  { asm volatile("cp.async.wait_group 0;" ::: "memory"); }

// ============================================================================
// Split fp32 -> bf16 hi + bf16 lo (elementwise)
// ============================================================================
__global__ void asplit_k(const float* __restrict__ A, bf16* __restrict__ H,
                         bf16* __restrict__ L, int n)
{
    int i = blockIdx.x * blockDim.x + threadIdx.x;
    if (i >= n) return;
    float v = A[i];
    bf16 h = __float2bfloat16_rn(v);
    H[i] = h;
    L[i] = __float2bfloat16_rn(v - __bfloat162float(h));
}

// ============================================================================
// Transpose + split: W[K,N] fp32 -> Th[N,K], Tl[N,K] bf16
// ============================================================================
__global__ void wsplit_t_k(const float* __restrict__ W, bf16* __restrict__ Th,
                           bf16* __restrict__ Tl, int K, int N)
{
    __shared__ float t[32][33];
    int n0 = blockIdx.x * 32, k0 = blockIdx.y * 32;
    int tx = threadIdx.x, ty = threadIdx.y;  // 32 x 8
#pragma unroll
    for (int j = 0; j < 32; j += 8)
        t[ty + j][tx] = W[(size_t)(k0 + ty + j) * N + n0 + tx];
    __syncthreads();
#pragma unroll
    for (int j = 0; j < 32; j += 8) {
        float v = t[tx][ty + j];
        bf16 h = __float2bfloat16_rn(v);
        size_t o = (size_t)(n0 + ty + j) * K + k0 + tx;
        Th[o] = h;
        Tl[o] = __float2bfloat16_rn(v - __bfloat162float(h));
    }
}

// ============================================================================
// RoPE + split: fp32 t (post-GEMM) -> bf16 hi/lo, rotated. total = #pairs.
// ============================================================================
__global__ void rope_split_k(const float* __restrict__ t, const float* __restrict__ cs,
                             const float* __restrict__ sn, bf16* __restrict__ H,
                             bf16* __restrict__ L, int nheads, int total)
{
    int idx = blockIdx.x * blockDim.x + threadIdx.x;
    if (idx >= total) return;
    int p = idx & 63;
    int s = ((idx >> 6) / nheads) % SEQ;
    float c = cs[s * 64 + p];
    float si = sn[s * 64 + p];
    int base = idx * 2;
    float tr = t[base], ti = t[base + 1];
    float a = tr * c - ti * si;
    float b2 = tr * si + ti * c;
    bf16 ah = __float2bfloat16_rn(a);
    bf16 bh = __float2bfloat16_rn(b2);
    H[base] = ah;     L[base] = __float2bfloat16_rn(a - __bfloat162float(ah));
    H[base + 1] = bh; L[base + 1] = __float2bfloat16_rn(b2 - __bfloat162float(bh));
}

// ============================================================================
// bf16-split GEMM on mma.sync + cp.async 2-stage pipeline.
// C[M,N](f32) = (Ah+Al)[M,K] x (Bh+Bl)[N,K]^T
// 128x128 tile, BK=32, 256 threads, warp grid 2(M)x4(N), warp tile 64x32.
// ============================================================================
#define GSTR 40                         // row stride elems (80B, 16B-aligned)
#define GSTG (4 * 128 * GSTR)           // elems per stage
#define GAL_B (128 * GSTR * 2)          // byte offset of Al within stage
#define GBH_B (2 * 128 * GSTR * 2)
#define GBL_B (3 * 128 * GSTR * 2)
#define GEMM_SMEM_B (2 * GSTG * 2)      // 81920 bytes

__global__ __launch_bounds__(256) void gemm_mma(const bf16* __restrict__ Ah,
                                                const bf16* __restrict__ Al,
                                                const bf16* __restrict__ Bh,
                                                const bf16* __restrict__ Bl,
                                                float* __restrict__ C,
                                                int M, int N, int K)
{
    extern __shared__ bf16 gsm[];

    const int tid = threadIdx.x, lane = tid & 31, warp = tid >> 5;
    const int wm = warp >> 2;       // 0..1 -> M offset wm*64
    const int wn = warp & 3;        // 0..3 -> N offset wn*32
    const int mB = blockIdx.y * 128, nB = blockIdx.x * 128;

    float c[4][4][4];
#pragma unroll
    for (int i = 0; i < 4; i++)
#pragma unroll
        for (int j = 0; j < 4; j++)
#pragma unroll
            for (int e = 0; e < 4; e++) c[i][j][e] = 0.f;

    auto copy_stage = [&](int kk, int st) {
        bf16* sb = gsm + st * GSTG;
#pragma unroll
        for (int j = 0; j < 2; j++) {
            int ch = tid + j * 256;
            int r = ch >> 2, kc8 = (ch & 3) * 8;
            uint32_t sa = smem_u32(sb + r * GSTR + kc8);
            size_t ga = (size_t)(mB + r) * K + kk + kc8;
            size_t gb = (size_t)(nB + r) * K + kk + kc8;
            cpa16(sa,          &Ah[ga]);
            cpa16(sa + GAL_B,  &Al[ga]);
            cpa16(sa + GBH_B,  &Bh[gb]);
            cpa16(sa + GBL_B,  &Bl[gb]);
        }
    };

    const int nk = K / 32;
    copy_stage(0, 0);
    cpa_commit();

    for (int i = 0; i < nk; i++) {
        cpa_wait0();
        __syncthreads();
        if (i + 1 < nk) { copy_stage((i + 1) * 32, (i + 1) & 1); cpa_commit(); }

        bf16* sb = gsm + (i & 1) * GSTG;
        bf16* sAh_ = sb;
        bf16* sAl_ = sb + 128 * GSTR;
        bf16* sBh_ = sb + 2 * 128 * GSTR;
        bf16* sBl_ = sb + 3 * 128 * GSTR;

#pragma unroll
        for (int ks = 0; ks < 2; ks++) {
            uint32_t fAh[4][4], fAl[4][4], fBh[2][4], fBl[2][4];
#pragma unroll
            for (int mt = 0; mt < 4; mt++) {
                int e = (wm * 64 + mt * 16 + (lane & 15)) * GSTR + ks * 16 + (lane >> 4) * 8;
                ldsm4(fAh[mt], smem_u32(&sAh_[e]));
                ldsm4(fAl[mt], smem_u32(&sAl_[e]));
            }
            {
                const int m = lane >> 3;
#pragma unroll
                for (int p = 0; p < 2; p++) {
                    int e = (wn * 32 + p * 16 + (m >> 1) * 8 + (lane & 7)) * GSTR
                          + ks * 16 + (m & 1) * 8;
                    ldsm4(fBh[p], smem_u32(&sBh_[e]));
                    ldsm4(fBl[p], smem_u32(&sBl_[e]));
                }
            }
#pragma unroll
            for (int mt = 0; mt < 4; mt++)
#pragma unroll
                for (int nt = 0; nt < 4; nt++) {
                    const int p = nt >> 1, off = (nt & 1) * 2;
                    mma_bf16(c[mt][nt], fAh[mt], &fBh[p][off]);
                    mma_bf16(c[mt][nt], fAh[mt], &fBl[p][off]);
                    mma_bf16(c[mt][nt], fAl[mt], &fBh[p][off]);
                }
        }
    }

    // epilogue
#pragma unroll
    for (int mt = 0; mt < 4; mt++)
#pragma unroll
        for (int nt = 0; nt < 4; nt++) {
            int row = mB + wm * 64 + mt * 16 + (lane >> 2);
            int col = nB + wn * 32 + nt * 8 + (lane & 3) * 2;
            float2 v0 = {c[mt][nt][0], c[mt][nt][1]};
            float2 v1 = {c[mt][nt][2], c[mt][nt][3]};
            *(float2*)&C[(size_t)row * N + col] = v0;
            *(float2*)&C[(size_t)(row + 8) * N + col] = v1;
        }
}

// ============================================================================
// Flash attention on mma.sync, bf16-split, cp.async 2-stage KV pipeline.
// BQ=128 (warp = 16 rows), BKV=64. Q/K smem K-major (ldmatrix x4),
// V natural [key][d] via ldmatrix x4.trans. P stays in registers.
// Writes bf16 hi/lo attention output for the final GEMM.
// ============================================================================
#define FSTR 136                       // 128 + 8 pad (272B rows)
#define FQH 0
#define FQL (128 * FSTR)
#define KVBASE (2 * 128 * FSTR)        // 34816 elems
#define KVSTG (4 * 64 * FSTR)          // 34816 elems per stage
#define FKL_B (64 * FSTR * 2)          // byte offsets within stage
#define FVH_B (2 * 64 * FSTR * 2)
#define FVL_B (3 * 64 * FSTR * 2)
#define FSM_ELEMS (KVBASE + 2 * KVSTG) // 104448 elems = 208896 B

__global__ __launch_bounds__(256) void flash_mma(const bf16* __restrict__ Qh,
                                                 const bf16* __restrict__ Ql,
                                                 const bf16* __restrict__ Kh,
                                                 const bf16* __restrict__ Kl,
                                                 const bf16* __restrict__ Vh,
                                                 const bf16* __restrict__ Vl,
                                                 bf16* __restrict__ Oh,
                                                 bf16* __restrict__ Ol)
{
    extern __shared__ bf16 fsm[];
    const int tid = threadIdx.x, lane = tid & 31, warp = tid >> 5;
    const int qt = blockIdx.x, h = blockIdx.y, b = blockIdx.z;
    const int q0 = qt * 128;
    const int khead = h >> 2;
    const float scale = 0.08838834764831845f;

    // load Q tile (128 x 128, hi+lo) with plain stores (once per CTA)
    for (int cidx = tid; cidx < 2048; cidx += 256) {
        int row = cidx >> 4, kc = (cidx & 15) * 8;
        size_t g = (size_t)(b * SEQ + q0 + row) * (NH * HD) + h * HD + kc;
        int s = row * FSTR + kc;
        *(uint4*)&fsm[FQH + s] = *(const uint4*)&Qh[g];
        *(uint4*)&fsm[FQL + s] = *(const uint4*)&Ql[g];
    }

    auto copy_kv = [&](int t, int st) {
        const int k0 = t * 64;
        const size_t gbase = (size_t)(b * SEQ + k0) * (NKV * HD) + khead * HD;
        uint32_t s0 = smem_u32(fsm + KVBASE + st * KVSTG);
#pragma unroll
        for (int j = 0; j < 4; j++) {
            int ch = tid + j * 256;            // 0..1023
            int r = ch >> 4, kc8 = (ch & 15) * 8;
            size_t g = gbase + (size_t)r * (NKV * HD) + kc8;
            uint32_t so = (uint32_t)(r * FSTR + kc8) * 2;
            cpa16(s0 + so,          &Kh[g]);
            cpa16(s0 + FKL_B + so,  &Kl[g]);
            cpa16(s0 + FVH_B + so,  &Vh[g]);
            cpa16(s0 + FVL_B + so,  &Vl[g]);
        }
    };

    float o[16][4];
#pragma unroll
    for (int i = 0; i < 16; i++)
#pragma unroll
        for (int e = 0; e < 4; e++) o[i][e] = 0.f;
    float mrow[2] = {-1e30f, -1e30f}, lrow[2] = {0.f, 0.f};

    const int ntiles = 2 * qt + 2;
    copy_kv(0, 0);
    cpa_commit();

    for (int t = 0; t < ntiles; t++) {
        cpa_wait0();
        __syncthreads();
        if (t + 1 < ntiles) { copy_kv(t + 1, (t + 1) & 1); cpa_commit(); }

        const int k0 = t * 64;
        bf16* sKH = fsm + KVBASE + (t & 1) * KVSTG;
        bf16* sKL = sKH + 64 * FSTR;
        bf16* sVH = sKH + 2 * 64 * FSTR;
        bf16* sVL = sKH + 3 * 64 * FSTR;

        // ---- S = Q K^T (warp rows x 64 keys), 3-product split ----
        float s[8][4];
#pragma unroll
        for (int i = 0; i < 8; i++)
#pragma unroll
            for (int e = 0; e < 4; e++) s[i][e] = 0.f;

#pragma unroll
        for (int ks = 0; ks < 8; ks++) {
            uint32_t qfh[4], qfl[4];
            int qa = (warp * 16 + (lane & 15)) * FSTR + ks * 16 + (lane >> 4) * 8;
            ldsm4(qfh, smem_u32(&fsm[FQH + qa]));
            ldsm4(qfl, smem_u32(&fsm[FQL + qa]));
            const int m = lane >> 3;
#pragma unroll
            for (int p = 0; p < 4; p++) {
                uint32_t kbh[4], kbl[4];
                int ka = (p * 16 + (m >> 1) * 8 + (lane & 7)) * FSTR + ks * 16 + (m & 1) * 8;
                ldsm4(kbh, smem_u32(&sKH[ka]));
                ldsm4(kbl, smem_u32(&sKL[ka]));
                mma_bf16(s[p * 2],     qfh, &kbh[0]);
                mma_bf16(s[p * 2],     qfh, &kbl[0]);
                mma_bf16(s[p * 2],     qfl, &kbh[0]);
                mma_bf16(s[p * 2 + 1], qfh, &kbh[2]);
                mma_bf16(s[p * 2 + 1], qfh, &kbl[2]);
                mma_bf16(s[p * 2 + 1], qfl, &kbh[2]);
            }
        }

        // ---- scale + causal mask ----
        const int r0 = q0 + warp * 16 + (lane >> 2);
        const bool needmask = (t >= ntiles - 2);
#pragma unroll
        for (int nt = 0; nt < 8; nt++) {
#pragma unroll
            for (int e = 0; e < 4; e++) {
                float v = s[nt][e] * scale;
                if (needmask) {
                    int col = k0 + nt * 8 + (lane & 3) * 2 + (e & 1);
                    int row = r0 + ((e >> 1) << 3);
                    if (col > row) v = -1e30f;
                }
                s[nt][e] = v;
            }
        }

        // ---- online softmax (rows r0 and r0+8, reduced over quad lanes) ----
        float mx0 = -1e30f, mx1 = -1e30f;
#pragma unroll
        for (int nt = 0; nt < 8; nt++) {
            mx0 = fmaxf(mx0, fmaxf(s[nt][0], s[nt][1]));
            mx1 = fmaxf(mx1, fmaxf(s[nt][2], s[nt][3]));
        }
        mx0 = fmaxf(mx0, __shfl_xor_sync(0xffffffff, mx0, 1));
        mx0 = fmaxf(mx0, __shfl_xor_sync(0xffffffff, mx0, 2));
        mx1 = fmaxf(mx1, __shfl_xor_sync(0xffffffff, mx1, 1));
        mx1 = fmaxf(mx1, __shfl_xor_sync(0xffffffff, mx1, 2));
        float mn0 = fmaxf(mrow[0], mx0), mn1 = fmaxf(mrow[1], mx1);
        float f0 = __expf(mrow[0] - mn0), f1 = __expf(mrow[1] - mn1);

        float sum0 = 0.f, sum1 = 0.f;
#pragma unroll
        for (int nt = 0; nt < 8; nt++) {
            s[nt][0] = __expf(s[nt][0] - mn0);
            s[nt][1] = __expf(s[nt][1] - mn0);
            s[nt][2] = __expf(s[nt][2] - mn1);
            s[nt][3] = __expf(s[nt][3] - mn1);
            sum0 += s[nt][0] + s[nt][1];
            sum1 += s[nt][2] + s[nt][3];
        }
        sum0 += __shfl_xor_sync(0xffffffff, sum0, 1);
        sum0 += __shfl_xor_sync(0xffffffff, sum0, 2);
        sum1 += __shfl_xor_sync(0xffffffff, sum1, 1);
        sum1 += __shfl_xor_sync(0xffffffff, sum1, 2);
        lrow[0] = lrow[0] * f0 + sum0;
        lrow[1] = lrow[1] * f1 + sum1;
        mrow[0] = mn0;
        mrow[1] = mn1;

        // ---- rescale O ----
#pragma unroll
        for (int nt = 0; nt < 16; nt++) {
            o[nt][0] *= f0; o[nt][1] *= f0;
            o[nt][2] *= f1; o[nt][3] *= f1;
        }

        // ---- O += P V : P from S fragments (hi + lo split) ----
#pragma unroll
        for (int ks = 0; ks < 4; ks++) {
            uint32_t ph[4], pl[4];
#pragma unroll
            for (int half = 0; half < 2; half++) {
                int ti2 = 2 * ks + half;
                bf16 h0 = __float2bfloat16_rn(s[ti2][0]);
                bf16 h1 = __float2bfloat16_rn(s[ti2][1]);
                bf16 h2 = __float2bfloat16_rn(s[ti2][2]);
                bf16 h3 = __float2bfloat16_rn(s[ti2][3]);
                ph[2 * half]     = pack2bf(h0, h1);
                ph[2 * half + 1] = pack2bf(h2, h3);
                pl[2 * half]     = pack2bf(__float2bfloat16_rn(s[ti2][0] - __bfloat162float(h0)),
                                           __float2bfloat16_rn(s[ti2][1] - __bfloat162float(h1)));
                pl[2 * half + 1] = pack2bf(__float2bfloat16_rn(s[ti2][2] - __bfloat162float(h2)),
                                           __float2bfloat16_rn(s[ti2][3] - __bfloat162float(h3)));
            }
            const int m = lane >> 3;
#pragma unroll
            for (int p = 0; p < 8; p++) {
                uint32_t vfh[4], vfl[4];
                int va = (ks * 16 + (m & 1) * 8 + (lane & 7)) * FSTR + (p * 2 + (m >> 1)) * 8;
                ldsm4t(vfh, smem_u32(&sVH[va]));
                ldsm4t(vfl, smem_u32(&sVL[va]));
                mma_bf16(o[p * 2],     ph, &vfh[0]);
                mma_bf16(o[p * 2],     ph, &vfl[0]);
                mma_bf16(o[p * 2],     pl, &vfh[0]);
                mma_bf16(o[p * 2 + 1], ph, &vfh[2]);
                mma_bf16(o[p * 2 + 1], ph, &vfl[2]);
                mma_bf16(o[p * 2 + 1], pl, &vfh[2]);
            }
        }
    }

    // ---- finalize: divide by l, write bf16 hi/lo ----
    float inv0 = 1.f / lrow[0], inv1 = 1.f / lrow[1];
    const size_t tok0 = (size_t)(b * SEQ + q0 + warp * 16 + (lane >> 2));
#pragma unroll
    for (int nt = 0; nt < 16; nt++) {
        int col = h * HD + nt * 8 + (lane & 3) * 2;
        float v0 = o[nt][0] * inv0, v1 = o[nt][1] * inv0;
        float v2 = o[nt][2] * inv1, v3 = o[nt][3] * inv1;
        bf16 h0 = __float2bfloat16_rn(v0), h1 = __float2bfloat16_rn(v1);
        bf16 h2 = __float2bfloat16_rn(v2), h3 = __float2bfloat16_rn(v3);
        size_t a0 = tok0 * EMB + col;
        size_t a1 = (tok0 + 8) * EMB + col;
        *(uint32_t*)&Oh[a0] = pack2bf(h0, h1);
        *(uint32_t*)&Oh[a1] = pack2bf(h2, h3);
        *(uint32_t*)&Ol[a0] = pack2bf(__float2bfloat16_rn(v0 - __bfloat162float(h0)),
                                      __float2bfloat16_rn(v1 - __bfloat162float(h1)));
        *(uint32_t*)&Ol[a1] = pack2bf(__float2bfloat16_rn(v2 - __bfloat162float(h2)),
                                      __float2bfloat16_rn(v3 - __bfloat162float(h3)));
    }
}

// ============================================================================
// launch
// ============================================================================
extern "C" void kernel_launch(void* const* d_in, const int* in_sizes, int n_in,
                              void* d_out, int out_size)
{
    const float* x  = (const float*)d_in[0];
    const float* cs = (const float*)d_in[1];
    const float* sn = (const float*)d_in[2];
    const float* wq = (const float*)d_in[3];
    const float* wk = (const float*)d_in[4];
    const float* wv = (const float*)d_in[5];
    const float* wo = (const float*)d_in[6];
    float* out = (float*)d_out;

    float *q, *k, *v;
    cudaGetSymbolAddress((void**)&q, g_q);
    cudaGetSymbolAddress((void**)&k, g_k);
    cudaGetSymbolAddress((void**)&v, g_v);

    bf16 *xh, *xl, *qh, *ql, *kh, *kl, *vh, *vl, *ath, *atl;
    bf16 *wqth, *wqtl, *wkth, *wktl, *wvth, *wvtl, *woth, *wotl;
    cudaGetSymbolAddress((void**)&xh,  g_xh);
    cudaGetSymbolAddress((void**)&xl,  g_xl);
    cudaGetSymbolAddress((void**)&qh,  g_qh);
    cudaGetSymbolAddress((void**)&ql,  g_ql);
    cudaGetSymbolAddress((void**)&kh,  g_kh);
    cudaGetSymbolAddress((void**)&kl,  g_kl);
    cudaGetSymbolAddress((void**)&vh,  g_vh);
    cudaGetSymbolAddress((void**)&vl,  g_vl);
    cudaGetSymbolAddress((void**)&ath, g_ath);
    cudaGetSymbolAddress((void**)&atl, g_atl);
    cudaGetSymbolAddress((void**)&wqth, g_wqth);
    cudaGetSymbolAddress((void**)&wqtl, g_wqtl);
    cudaGetSymbolAddress((void**)&wkth, g_wkth);
    cudaGetSymbolAddress((void**)&wktl, g_wktl);
    cudaGetSymbolAddress((void**)&wvth, g_wvth);
    cudaGetSymbolAddress((void**)&wvtl, g_wvtl);
    cudaGetSymbolAddress((void**)&woth, g_woth);
    cudaGetSymbolAddress((void**)&wotl, g_wotl);

    const int fsmem = FSM_ELEMS * (int)sizeof(bf16);   // 208896 B
    cudaFuncSetAttribute(flash_mma, cudaFuncAttributeMaxDynamicSharedMemorySize, fsmem);
    cudaFuncSetAttribute(gemm_mma, cudaFuncAttributeMaxDynamicSharedMemorySize, GEMM_SMEM_B);

    const int M = BSZ * SEQ;   // 4096
    const int NKVD = NKV * HD; // 512

    // splits
    asplit_k<<<(M * EMB + 255) / 256, 256>>>(x, xh, xl, M * EMB);
    wsplit_t_k<<<dim3(EMB / 32, EMB / 32),  dim3(32, 8)>>>(wq, wqth, wqtl, EMB, EMB);
    wsplit_t_k<<<dim3(NKVD / 32, EMB / 32), dim3(32, 8)>>>(wk, wkth, wktl, EMB, NKVD);
    wsplit_t_k<<<dim3(NKVD / 32, EMB / 32), dim3(32, 8)>>>(wv, wvth, wvtl, EMB, NKVD);
    wsplit_t_k<<<dim3(EMB / 32, EMB / 32),  dim3(32, 8)>>>(wo, woth, wotl, EMB, EMB);

    // QKV projections (tensor cores)
    gemm_mma<<<dim3(EMB / 128, M / 128), 256, GEMM_SMEM_B>>>(xh, xl, wqth, wqtl, q, M, EMB, EMB);
    gemm_mma<<<dim3(NKVD / 128, M / 128), 256, GEMM_SMEM_B>>>(xh, xl, wkth, wktl, k, M, NKVD, EMB);
    gemm_mma<<<dim3(NKVD / 128, M / 128), 256, GEMM_SMEM_B>>>(xh, xl, wvth, wvtl, v, M, NKVD, EMB);

    // rope + split to bf16
    rope_split_k<<<(M * NH * 64 + 255) / 256, 256>>>(q, cs, sn, qh, ql, NH, M * NH * 64);
    rope_split_k<<<(M * NKV * 64 + 255) / 256, 256>>>(k, cs, sn, kh, kl, NKV, M * NKV * 64);
    asplit_k<<<(M * NKVD + 255) / 256, 256>>>(v, vh, vl, M * NKVD);

    // attention (tensor cores), writes split bf16 output
    flash_mma<<<dim3(SEQ / 128, NH, BSZ), 256, fsmem>>>(qh, ql, kh, kl, vh, vl, ath, atl);

    // out projection (tensor cores)
    gemm_mma<<<dim3(EMB / 128, M / 128), 256, GEMM_SMEM_B>>>(ath, atl, woth, wotl, out, M, EMB, EMB);
}